// round 10
// baseline (speedup 1.0000x reference)
#include <cuda_runtime.h>
#include <math.h>

#define N_ATOMS 2048
#define HID     32
#define CUTOFF2 6.25f
#define JCHUNK  32
#define NDIAG   64            // 8 diagonal tiles x 8 chunks, weight 0.5
#define NBLK    288           // 64 diag + 224 off-diag
#define BUF     256           // per-warp hit buffer (mean ~26)

__device__ double   g_energy = 0.0;
__device__ unsigned g_done   = 0;

// cumulative off-diagonal chunk counts per i-tile (count ti = (7-ti)*8)
__constant__ int c_off[9] = {0, 56, 104, 144, 176, 200, 216, 224, 224};

__device__ __forceinline__ float tanh_fast(float x) {
    float y;
    asm("tanh.approx.f32 %0, %1;" : "=f"(y) : "f"(x));
    return y;
}
__device__ __forceinline__ float sqrt_fast(float x) {
    float y;
    asm("sqrt.approx.f32 %0, %1;" : "=f"(y) : "f"(x));
    return y;
}

__global__ __launch_bounds__(256, 4) void pair_kernel(
    const float* __restrict__ xyz,
    const float* __restrict__ cell,
    const float* __restrict__ W1,
    const float* __restrict__ b1,
    const float* __restrict__ W2,
    const float* __restrict__ b2,
    float* __restrict__ out)
{
    __shared__ float4 sj[JCHUNK];       // j positions
    __shared__ float4 sw[HID];          // (W1, b1, W2, 0)
    __shared__ float  sdist[8][BUF];    // per-warp hit dsq buffer
    __shared__ float  swarp[8];

    const int tid  = threadIdx.x;
    const int lane = tid & 31;
    const int warp = tid >> 5;
    const int blk  = blockIdx.x;

    // ---- block -> (i_tile, j0, weight) -------------------------------
    int   ti, j0;
    float w;
    if (blk < NDIAG) {                   // diagonal band: 256x32, w=0.5
        ti = blk >> 3;
        j0 = ti * 256 + (blk & 7) * JCHUNK;
        w  = 0.5f;
    } else {                             // strictly above diagonal, w=1
        int b = blk - NDIAG;
        ti = 0;
        #pragma unroll
        for (int k = 0; k < 7; k++)
            if (b >= c_off[k + 1]) ti = k + 1;
        j0 = (ti + 1) * 256 + (b - c_off[ti]) * JCHUNK;
        w  = 1.0f;
    }
    const int i = ti * 256 + tid;

    if (tid < JCHUNK) {
        int j = j0 + tid;
        sj[tid] = make_float4(xyz[3*j], xyz[3*j+1], xyz[3*j+2], 0.f);
    } else if (tid < JCHUNK + HID) {
        int k = tid - JCHUNK;
        sw[k] = make_float4(W1[k], b1[k], W2[k], 0.f);
    }
    __syncthreads();

    const float Lx = cell[0], Ly = cell[1], Lz = cell[2];
    const float xi = xyz[3*i], yi = xyz[3*i+1], zi = xyz[3*i+2];
    const float b2v = b2[0];

    // ---- Phase A: distances + warp-compacted hit recording -----------
    int nhit = 0;   // uniform across warp

    #pragma unroll
    for (int jj = 0; jj < JCHUNK; jj++) {
        float4 p = sj[jj];
        float ax = fabsf(p.x - xi);
        float ay = fabsf(p.y - yi);
        float az = fabsf(p.z - zi);
        float wx = fminf(ax, Lx - ax);
        float wy = fminf(ay, Ly - ay);
        float wz = fminf(az, Lz - az);
        float dsq = fmaf(wx, wx, fmaf(wy, wy, wz * wz));

        bool hit = (dsq > 0.0f) && (dsq < CUTOFF2);
        unsigned m = __ballot_sync(0xFFFFFFFFu, hit);
        if (hit) {
            int off = nhit + __popc(m & ((1u << lane) - 1u));
            if (off < BUF) sdist[warp][off] = dsq;
        }
        nhit += __popc(m);
    }
    if (nhit > BUF) nhit = BUF;
    __syncwarp();

    // ---- Phase B: exact MLP on compacted hits ------------------------
    float acc = 0.0f;
    for (int h = lane; h < nhit; h += 32) {
        float dsq = sdist[warp][h];
        float d = sqrt_fast(dsq);
        float e = b2v;
        #pragma unroll
        for (int k = 0; k < HID; k++) {
            float4 wv = sw[k];
            e = fmaf(tanh_fast(fmaf(d, wv.x, wv.y)), wv.z, e);
        }
        acc += e;
    }
    acc *= w;

    // ---- Reduce + finish ---------------------------------------------
    #pragma unroll
    for (int off = 16; off > 0; off >>= 1)
        acc += __shfl_down_sync(0xFFFFFFFFu, acc, off);

    if (lane == 0) swarp[warp] = acc;
    __syncthreads();

    if (warp == 0) {
        float v = (lane < 8) ? swarp[lane] : 0.0f;
        #pragma unroll
        for (int off = 4; off > 0; off >>= 1)
            v += __shfl_down_sync(0xFFFFFFFFu, v, off);
        if (lane == 0) {
            atomicAdd(&g_energy, (double)v);
            __threadfence();
            unsigned old = atomicAdd(&g_done, 1u);
            if (old == NBLK - 1) {
                __threadfence();
                double esum = __longlong_as_double(
                    atomicExch((unsigned long long*)&g_energy, 0ULL));
                out[0] = (float)esum;       // triangle: no halving
                __threadfence();
                atomicExch(&g_done, 0u);
            }
        }
    }
}

extern "C" void kernel_launch(void* const* d_in, const int* in_sizes, int n_in,
                              void* d_out, int out_size)
{
    const float* xyz  = (const float*)d_in[0];
    const float* cell = (const float*)d_in[1];
    const float* W1   = (const float*)d_in[2];
    const float* b1   = (const float*)d_in[3];
    const float* W2   = (const float*)d_in[4];
    const float* b2   = (const float*)d_in[5];
    float* out = (float*)d_out;

    pair_kernel<<<NBLK, 256>>>(xyz, cell, W1, b1, W2, b2, out);
}

// round 11
// speedup vs baseline: 1.3375x; 1.3375x over previous
#include <cuda_runtime.h>
#include <math.h>

#define N_ATOMS 2048
#define HID     32
#define CUTOFF2 6.25f
#define JCHUNK  16
#define LUT_N   16384         // nearest-bin LUT over dsq in [0, CUTOFF2]; +1 guard
#define NDIAG   128           // 8 diagonal tiles x 16 chunks, weight 0.5
#define NBLK    576           // 128 diag + 448 off-diag

__device__ double   g_energy = 0.0;
__device__ unsigned g_done   = 0;
__device__ float    g_lut[LUT_N + 1];

// cumulative off-diagonal chunk counts per i-tile (count ti = 112 - 16*ti)
__constant__ int c_off[9] = {0, 112, 208, 288, 352, 400, 432, 448, 448};

__device__ __forceinline__ float tanh_fast(float x) {
    float y;
    asm("tanh.approx.f32 %0, %1;" : "=f"(y) : "f"(x));
    return y;
}
__device__ __forceinline__ float sqrt_fast(float x) {
    float y;
    asm("sqrt.approx.f32 %0, %1;" : "=f"(y) : "f"(x));
    return y;
}

// Nearest-bin LUT: entry i = f(sqrt(s_i)), s_i = (i + 0 .. centered by RNI at use).
// Guard entry LUT_N = 0: clamped misses contribute exactly zero.
__global__ __launch_bounds__(256) void lut_kernel(
    const float* __restrict__ W1, const float* __restrict__ b1,
    const float* __restrict__ W2, const float* __restrict__ b2)
{
    const int idx = blockIdx.x * blockDim.x + threadIdx.x;
    if (idx <= LUT_N) {
        if (idx == LUT_N) {
            g_lut[idx] = 0.0f;
        } else {
            const float ds = CUTOFF2 / (float)LUT_N;
            const float d0 = sqrt_fast((float)idx * ds);   // bin-center via RNI index
            float f0 = b2[0];
            #pragma unroll
            for (int k = 0; k < HID; k++)
                f0 = fmaf(tanh_fast(fmaf(d0, W1[k], b1[k])), W2[k], f0);
            g_lut[idx] = f0;
        }
    }
    __threadfence();
    cudaTriggerProgrammaticLaunchCompletion();
}

__global__ __launch_bounds__(256, 6) void pair_kernel(
    const float* __restrict__ xyz,
    const float* __restrict__ cell,
    float* __restrict__ out)
{
    __shared__ float4 sj[JCHUNK];
    __shared__ float  swarp[8];

    const int tid = threadIdx.x;
    const int blk = blockIdx.x;

    // ---- block -> (i_tile, j0, weight) -------------------------------
    int   ti, j0;
    float w;
    if (blk < NDIAG) {                    // diagonal band: full 256x16, w=0.5
        ti = blk >> 4;
        j0 = ti * 256 + (blk & 15) * JCHUNK;
        w  = 0.5f;
    } else {                              // strictly above the diagonal, w=1
        int b = blk - NDIAG;
        ti = 0;
        #pragma unroll
        for (int k = 0; k < 7; k++)
            if (b >= c_off[k + 1]) ti = k + 1;
        j0 = (ti + 1) * 256 + (b - c_off[ti]) * JCHUNK;
        w  = 1.0f;
    }
    const int i = ti * 256 + tid;

    // Prologue: runs concurrently with lut_kernel (no g_lut dependence).
    if (tid < JCHUNK) {
        int j = j0 + tid;
        sj[tid] = make_float4(xyz[3*j], xyz[3*j+1], xyz[3*j+2], 0.f);
    }
    const float Lx = cell[0], Ly = cell[1], Lz = cell[2];
    const float xi = xyz[3*i], yi = xyz[3*i+1], zi = xyz[3*i+2];
    __syncthreads();

    // Gate on lut_kernel's triggered completion before any g_lut read.
    cudaGridDependencySynchronize();

    const float sscale = (float)LUT_N / CUTOFF2;   // dsq -> bin
    const float tmax   = (float)LUT_N;             // guard bin (value 0)

    float acc = 0.0f;

    #pragma unroll
    for (int jj = 0; jj < JCHUNK; jj++) {
        float4 p = sj[jj];
        // MIC magnitude per dim: |dx_mic| = min(|dx|, L - |dx|)  (|dx| < L)
        float ax = fabsf(p.x - xi);
        float ay = fabsf(p.y - yi);
        float az = fabsf(p.z - zi);
        float wx = fminf(ax, Lx - ax);
        float wy = fminf(ay, Ly - ay);
        float wz = fminf(az, Lz - az);
        float dsq = fmaf(wx, wx, fmaf(wy, wy, wz * wz));

        float t  = fminf(dsq * sscale, tmax);      // miss -> guard bin (0)
        int   it = __float2int_rn(t);              // nearest bin, single F2I.RNI
        acc += __ldg(&g_lut[it]);                  // unconditional
    }

    // self-pair (dsq = 0 -> bin 0 = f(0)) appears once per atom, in its diag chunk
    if ((unsigned)(i - j0) < (unsigned)JCHUNK)
        acc -= __ldg(&g_lut[0]);

    acc *= w;

    // warp reduce in float
    #pragma unroll
    for (int off = 16; off > 0; off >>= 1)
        acc += __shfl_down_sync(0xFFFFFFFFu, acc, off);

    const int lane = tid & 31;
    const int warp = tid >> 5;
    if (lane == 0) swarp[warp] = acc;
    __syncthreads();

    if (warp == 0) {
        float v = (lane < 8) ? swarp[lane] : 0.0f;
        #pragma unroll
        for (int off = 4; off > 0; off >>= 1)
            v += __shfl_down_sync(0xFFFFFFFFu, v, off);
        if (lane == 0) {
            atomicAdd(&g_energy, (double)v);
            __threadfence();
            unsigned old = atomicAdd(&g_done, 1u);
            if (old == NBLK - 1) {
                __threadfence();
                double esum = __longlong_as_double(
                    atomicExch((unsigned long long*)&g_energy, 0ULL));
                out[0] = (float)esum;          // triangle: no halving
                __threadfence();
                atomicExch(&g_done, 0u);
            }
        }
    }
}

extern "C" void kernel_launch(void* const* d_in, const int* in_sizes, int n_in,
                              void* d_out, int out_size)
{
    const float* xyz  = (const float*)d_in[0];
    const float* cell = (const float*)d_in[1];
    const float* W1   = (const float*)d_in[2];
    const float* b1   = (const float*)d_in[3];
    const float* W2   = (const float*)d_in[4];
    const float* b2   = (const float*)d_in[5];
    float* out = (float*)d_out;

    lut_kernel<<<(LUT_N + 1 + 255) / 256, 256>>>(W1, b1, W2, b2);

    // PDL: pair_kernel pre-launches while lut_kernel runs; CTAs block at
    // cudaGridDependencySynchronize() until lut triggers completion.
    cudaLaunchConfig_t cfg = {};
    cfg.gridDim  = dim3(NBLK, 1, 1);
    cfg.blockDim = dim3(256, 1, 1);
    cfg.dynamicSmemBytes = 0;
    cfg.stream = 0;
    cudaLaunchAttribute attr[1];
    attr[0].id = cudaLaunchAttributeProgrammaticStreamSerialization;
    attr[0].val.programmaticStreamSerializationAllowed = 1;
    cfg.attrs = attr;
    cfg.numAttrs = 1;
    cudaLaunchKernelEx(&cfg, pair_kernel, xyz, cell, out);
}